// round 14
// baseline (speedup 1.0000x reference)
#include <cuda_runtime.h>
#include <cstdint>

// Problem constants
constexpr int BATCH = 8;
constexpr int T = 2048;
constexpr int C = 512;                 // IN_CH = KEY = VAL = 512
constexpr int M_TOT = BATCH * T;       // 16384
constexpr int NCHUNK = 32;             // per-64-row-segment softmax partials
constexpr float SCALE = 0.044194173824159216f; // 1/sqrt(512)

constexpr int AK = 20;                 // padded k-stride for [m][k] smem tiles
constexpr int A_STG = 128 * AK;        // floats per A stage (2560)
constexpr int B_STG = 16 * 136;        // floats per B stage (2176)
constexpr int SMEM_AB  = 3 * (A_STG + B_STG) * 4;   // qkv / pv dynamic smem
constexpr int SMEM_AA  = 3 * (2 * A_STG) * 4;       // logits dynamic smem

// Scratch (device globals: allocation-free rule)
__device__ float g_q[M_TOT * C];       // pre-scaled by SCALE
__device__ float g_k[M_TOT * C];
__device__ float g_v[M_TOT * C];
__device__ float g_logits[(size_t)BATCH * T * T];   // exp(l - m_seg), 0 above diag
__device__ float g_pm[(size_t)NCHUNK * M_TOT];      // partial max -> then rescale factor f
__device__ float g_pd[(size_t)NCHUNK * M_TOT];      // partial denom

// ---------------------------------------------------------------------------
// helpers
// ---------------------------------------------------------------------------
__device__ __forceinline__ void mma_tf32(float d[4], const uint32_t a[4], const uint32_t b[2]) {
    asm volatile(
        "mma.sync.aligned.m16n8k8.row.col.f32.tf32.tf32.f32 "
        "{%0,%1,%2,%3}, {%4,%5,%6,%7}, {%8,%9}, {%0,%1,%2,%3};\n"
        : "+f"(d[0]), "+f"(d[1]), "+f"(d[2]), "+f"(d[3])
        : "r"(a[0]), "r"(a[1]), "r"(a[2]), "r"(a[3]), "r"(b[0]), "r"(b[1]));
}
__device__ __forceinline__ uint32_t smem_u32(const void* p) {
    return (uint32_t)__cvta_generic_to_shared(p);
}
__device__ __forceinline__ void ldsm4(uint32_t f[4], uint32_t addr) {
    asm volatile("ldmatrix.sync.aligned.m8n8.x4.shared.b16 {%0,%1,%2,%3}, [%4];"
                 : "=r"(f[0]), "=r"(f[1]), "=r"(f[2]), "=r"(f[3]) : "r"(addr));
}
#define CP16(dst, src) asm volatile("cp.async.ca.shared.global [%0], [%1], 16;" :: "r"(dst), "l"(src))
#define CP_COMMIT()    asm volatile("cp.async.commit_group;")
#define CP_WAIT(n)     asm volatile("cp.async.wait_group %0;" :: "n"(n))

// ---------------------------------------------------------------------------
// MMA consume: 128x128x16 CTA tile, 4 warps of 64x64.
// aAddr: smem addr of A stage base + per-lane ldmatrix offset (incl. mw).
// If BNK: bAddr likewise for [n][AK] B tile; else BsKN points at [16][136].
// ---------------------------------------------------------------------------
template<bool BNK>
__device__ __forceinline__ void mma_consume(uint32_t aAddr, uint32_t bAddr,
                                            const float* __restrict__ BsKN,
                                            int nw, int r, int c,
                                            float acc[4][8][4])
{
#pragma unroll
    for (int ks = 0; ks < 2; ++ks) {
        const int kkB = ks * 32;          // 8 floats -> 32 bytes
        uint32_t af[4][4], bf[8][2];
#pragma unroll
        for (int mi = 0; mi < 4; ++mi)
            ldsm4(af[mi], aAddr + mi * (16 * AK * 4) + kkB);
        if (BNK) {
#pragma unroll
            for (int p = 0; p < 4; ++p) {
                uint32_t t[4];
                ldsm4(t, bAddr + p * (16 * AK * 4) + kkB);
                bf[2 * p][0] = t[0]; bf[2 * p][1] = t[1];
                bf[2 * p + 1][0] = t[2]; bf[2 * p + 1][1] = t[3];
            }
        } else {
            const int kk = ks * 8;
#pragma unroll
            for (int ni = 0; ni < 8; ++ni) {
                const int n = nw + ni * 8 + r;
                bf[ni][0] = __float_as_uint(BsKN[(kk + c) * 136 + n]);
                bf[ni][1] = __float_as_uint(BsKN[(kk + c + 4) * 136 + n]);
            }
        }
#pragma unroll
        for (int mi = 0; mi < 4; ++mi)
#pragma unroll
            for (int ni = 0; ni < 8; ++ni)
                mma_tf32(acc[mi][ni], af[mi], bf[ni]);
    }
}

// pv variant: A fragments scaled by per-k rescale factors fv (f depends only
// on k within a warp since each 64-row warp tile sits in one 64-row segment).
__device__ __forceinline__ void mma_consume_f(uint32_t aAddr,
                                              const float* __restrict__ BsKN,
                                              int nw, int r, int c,
                                              const float fv[4],
                                              float acc[4][8][4])
{
#pragma unroll
    for (int ks = 0; ks < 2; ++ks) {
        const int kkB = ks * 32;
        const float fa = fv[ks * 2], fb = fv[ks * 2 + 1];
        uint32_t af[4][4], bf[8][2];
#pragma unroll
        for (int mi = 0; mi < 4; ++mi) {
            ldsm4(af[mi], aAddr + mi * (16 * AK * 4) + kkB);
            af[mi][0] = __float_as_uint(__uint_as_float(af[mi][0]) * fa);
            af[mi][1] = __float_as_uint(__uint_as_float(af[mi][1]) * fa);
            af[mi][2] = __float_as_uint(__uint_as_float(af[mi][2]) * fb);
            af[mi][3] = __float_as_uint(__uint_as_float(af[mi][3]) * fb);
        }
        const int kk = ks * 8;
#pragma unroll
        for (int ni = 0; ni < 8; ++ni) {
            const int n = nw + ni * 8 + r;
            bf[ni][0] = __float_as_uint(BsKN[(kk + c) * 136 + n]);
            bf[ni][1] = __float_as_uint(BsKN[(kk + c + 4) * 136 + n]);
        }
#pragma unroll
        for (int mi = 0; mi < 4; ++mi)
#pragma unroll
            for (int ni = 0; ni < 8; ++ni)
                mma_tf32(acc[mi][ni], af[mi], bf[ni]);
    }
}

// Fragment->global: acc[mi][ni][reg]:
//   row = rBase + mw + mi*16 + (lane>>2) + (reg>=2 ? 8 : 0)
//   col = cBase + nw + ni*8  + 2*(lane&3) + (reg&1)

// ---------------------------------------------------------------------------
// 1. QKV projection. 128 threads, 4 warps of 64x64; 3-stage cp.async ring.
//    Blocks (z==0, bx==0) additionally stream x into out[:, 0:512].
// ---------------------------------------------------------------------------
__global__ __launch_bounds__(128, 2)
void qkv_kernel(const float* __restrict__ x,
                const float* __restrict__ Wq, const float* __restrict__ bq,
                const float* __restrict__ Wk, const float* __restrict__ bk,
                const float* __restrict__ Wv, const float* __restrict__ bv,
                float* __restrict__ xout)
{
    extern __shared__ float dsm[];
    float* As = dsm;                  // [3][A_STG]
    float* Bs = dsm + 3 * A_STG;      // [3][B_STG]

    const float* W; const float* bias; float* out; float oscale;
    if (blockIdx.z == 0)      { W = Wq; bias = bq; out = g_q; oscale = SCALE; }
    else if (blockIdx.z == 1) { W = Wk; bias = bk; out = g_k; oscale = 1.0f; }
    else                      { W = Wv; bias = bv; out = g_v; oscale = 1.0f; }

    const int rBase = blockIdx.y * 128;
    const int cBase = blockIdx.x * 128;
    const int tid = threadIdx.x, lane = tid & 31, warp = tid >> 5;
    const int mw = (warp >> 1) * 64, nw = (warp & 1) * 64;
    const int r = lane >> 2, cc = lane & 3;
    const int quad = lane >> 3, qi = lane & 7;
    const uint32_t aLane = ((mw + (quad & 1) * 8 + qi) * AK + (quad >> 1) * 4) * 4;

    const int arow = tid;                      // 0..127, full 16-float row
    const int brow = tid >> 3, bcol = (tid & 7) * 16;
    const float* Asrc = x + (size_t)(rBase + arow) * C;
    const float* Bsrc = W + (size_t)brow * C + cBase + bcol;
    uint32_t adst[3], bdst[3], aAddrs[3];
#pragma unroll
    for (int s = 0; s < 3; ++s) {
        adst[s] = smem_u32(&As[s * A_STG + arow * AK]);
        bdst[s] = smem_u32(&Bs[s * B_STG + brow * 136 + bcol]);
        aAddrs[s] = smem_u32(&As[s * A_STG]) + aLane;
    }

    auto issue = [&](int st, int k0) {
#pragma unroll
        for (int j = 0; j < 4; ++j)
            CP16(adst[st] + j * 16, Asrc + k0 + j * 4);
#pragma unroll
        for (int j = 0; j < 4; ++j)
            CP16(bdst[st] + j * 16, Bsrc + (size_t)k0 * C + j * 4);
        CP_COMMIT();
    };

    const bool wx = (blockIdx.z == 0) && (blockIdx.x == 0);
    float acc[4][8][4] = {};
    constexpr int NIT = C / 16;
    issue(0, 0);
    issue(1, 16);
    for (int it = 0; it < NIT; ++it) {
        if (it + 1 < NIT) CP_WAIT(1); else CP_WAIT(0);
        __syncthreads();
        const int st = it % 3;
        if (it + 2 < NIT) issue((it + 2) % 3, (it + 2) * 16);
        if (wx) {
            const float* a = &As[st * A_STG + arow * AK];
            float* xo = xout + (size_t)(rBase + arow) * 1024 + it * 16;
#pragma unroll
            for (int j = 0; j < 4; ++j)
                *(float4*)(xo + j * 4) = *(const float4*)(a + j * 4);
        }
        mma_consume<false>(aAddrs[st], 0, &Bs[st * B_STG], nw, r, cc, acc);
    }

#pragma unroll
    for (int mi = 0; mi < 4; ++mi) {
#pragma unroll
        for (int ni = 0; ni < 8; ++ni) {
            const int row = rBase + mw + mi * 16 + r;
            const int col = cBase + nw + ni * 8 + 2 * cc;
            float b0 = bias[col], b1 = bias[col + 1];
            float2 lo, hi;
            lo.x = (acc[mi][ni][0] + b0) * oscale;
            lo.y = (acc[mi][ni][1] + b1) * oscale;
            hi.x = (acc[mi][ni][2] + b0) * oscale;
            hi.y = (acc[mi][ni][3] + b1) * oscale;
            *(float2*)&out[(size_t)row * C + col]       = lo;
            *(float2*)&out[(size_t)(row + 8) * C + col] = hi;
        }
    }
}

// ---------------------------------------------------------------------------
// 2. logits = q . k^T (3-stage ring, ldmatrix both operands).
//    Per-warp 64-row column-segment softmax; stores exp(l - m_seg), 0 above
//    diag; (m_seg, sum) partials to g_pm/g_pd[chunk = 2*by + (mw>>6)].
// ---------------------------------------------------------------------------
__global__ __launch_bounds__(128, 2)
void logits_kernel()
{
    const int bx = blockIdx.x, by = blockIdx.y, b = blockIdx.z;
    if (bx > by) return;
    extern __shared__ float dsm[];
    float* As = dsm;                  // [3][A_STG]
    float* Bn = dsm + 3 * A_STG;      // [3][A_STG]

    const int rBase = by * 128;
    const int cBase = bx * 128;
    const float* A  = g_q + (size_t)b * T * C;
    const float* Bm = g_k + (size_t)b * T * C;
    float* Cp = g_logits + (size_t)b * T * T;

    const int tid = threadIdx.x, lane = tid & 31, warp = tid >> 5;
    const int mw = (warp >> 1) * 64, nw = (warp & 1) * 64;
    const int r = lane >> 2, cc = lane & 3;
    const int quad = lane >> 3, qi = lane & 7;
    const uint32_t aLane = ((mw + (quad & 1) * 8 + qi) * AK + (quad >> 1) * 4) * 4;
    const uint32_t bLane = ((nw + (quad >> 1) * 8 + qi) * AK + (quad & 1) * 4) * 4;

    const int arow = tid;
    const float* Asrc = A  + (size_t)(rBase + arow) * C;
    const float* Bsrc = Bm + (size_t)(cBase + arow) * C;
    uint32_t adst[3], bdst[3], aAddrs[3], bAddrs[3];
#pragma unroll
    for (int s = 0; s < 3; ++s) {
        adst[s] = smem_u32(&As[s * A_STG + arow * AK]);
        bdst[s] = smem_u32(&Bn[s * A_STG + arow * AK]);
        aAddrs[s] = smem_u32(&As[s * A_STG]) + aLane;
        bAddrs[s] = smem_u32(&Bn[s * A_STG]) + bLane;
    }

    auto issue = [&](int st, int k0) {
#pragma unroll
        for (int j = 0; j < 4; ++j)
            CP16(adst[st] + j * 16, Asrc + k0 + j * 4);
#pragma unroll
        for (int j = 0; j < 4; ++j)
            CP16(bdst[st] + j * 16, Bsrc + k0 + j * 4);
        CP_COMMIT();
    };

    float acc[4][8][4] = {};
    constexpr int NIT = C / 16;
    issue(0, 0);
    issue(1, 16);
    for (int it = 0; it < NIT; ++it) {
        if (it + 1 < NIT) CP_WAIT(1); else CP_WAIT(0);
        __syncthreads();
        const int st = it % 3;
        if (it + 2 < NIT) issue((it + 2) % 3, (it + 2) * 16);
        mma_consume<true>(aAddrs[st], bAddrs[st], nullptr, nw, r, cc, acc);
    }

    // per-warp 64-row column-segment stats; acc -> exp(v - m_seg) in place
    const bool diag = (bx == by);
    float mcol[16], dcol[16];
#pragma unroll
    for (int ni = 0; ni < 8; ++ni) {
#pragma unroll
        for (int sub = 0; sub < 2; ++sub) {
            const int j = ni * 2 + sub;
            const int sl = nw + ni * 8 + 2 * cc + sub;   // column within tile
            float m = -1e30f;
#pragma unroll
            for (int mi = 0; mi < 4; ++mi)
#pragma unroll
                for (int h = 0; h < 2; ++h) {
                    const int tl = mw + mi * 16 + r + h * 8;
                    const float v = acc[mi][ni][h * 2 + sub];
                    if ((!diag || tl >= sl) && v > m) m = v;
                }
#pragma unroll
            for (int off = 4; off < 32; off <<= 1)
                m = fmaxf(m, __shfl_xor_sync(0xffffffffu, m, off));
            float d = 0.f;
#pragma unroll
            for (int mi = 0; mi < 4; ++mi)
#pragma unroll
                for (int h = 0; h < 2; ++h) {
                    const int tl = mw + mi * 16 + r + h * 8;
                    const float v = acc[mi][ni][h * 2 + sub];
                    const float p = (!diag || tl >= sl) ? __expf(v - m) : 0.0f;
                    acc[mi][ni][h * 2 + sub] = p;
                    d += p;
                }
#pragma unroll
            for (int off = 4; off < 32; off <<= 1)
                d += __shfl_xor_sync(0xffffffffu, d, off);
            mcol[j] = m; dcol[j] = d;
        }
    }

    // write p-hat tile
#pragma unroll
    for (int mi = 0; mi < 4; ++mi) {
#pragma unroll
        for (int ni = 0; ni < 8; ++ni) {
            const int row = rBase + mw + mi * 16 + r;
            const int col = cBase + nw + ni * 8 + 2 * cc;
            *(float2*)&Cp[(size_t)row * T + col]       = make_float2(acc[mi][ni][0], acc[mi][ni][1]);
            *(float2*)&Cp[(size_t)(row + 8) * T + col] = make_float2(acc[mi][ni][2], acc[mi][ni][3]);
        }
    }

    // write segment partials (chunk = 64-row granularity)
    if (r == 0) {
        const int chw = 2 * by + (mw >> 6);
#pragma unroll
        for (int j = 0; j < 16; ++j) {
            const int colg = cBase + nw + (j >> 1) * 8 + 2 * cc + (j & 1);
            g_pm[(size_t)chw * M_TOT + b * T + colg] = mcol[j];
            g_pd[(size_t)chw * M_TOT + b * T + colg] = dcol[j];
        }
    }
}

// ---------------------------------------------------------------------------
// 3. Merge segment partials; overwrite g_pm with rescale factors
//    f[ch][s] = exp(m_seg - cmax) / sum. Boundary chunk (fully masked) = 0.
// ---------------------------------------------------------------------------
__global__ void colmerge_kernel()
{
    const int i = blockIdx.x * blockDim.x + threadIdx.x;
    const int s = i & (T - 1);
    const int ch0 = s >> 6;
    float m = -1e30f, d = 0.f;
    for (int ch = ch0; ch < NCHUNK; ++ch) {
        float m2 = g_pm[(size_t)ch * M_TOT + i], d2 = g_pd[(size_t)ch * M_TOT + i];
        float nm = fmaxf(m, m2);
        d = d * __expf(m - nm) + d2 * __expf(m2 - nm);
        m = nm;
    }
    const float inv = 1.0f / d;
    for (int ch = ch0; ch < NCHUNK; ++ch) {
        float m2 = g_pm[(size_t)ch * M_TOT + i];
        g_pm[(size_t)ch * M_TOT + i] = __expf(m2 - m) * inv;
    }
    if (ch0 > 0) g_pm[(size_t)(ch0 - 1) * M_TOT + i] = 0.0f;  // read by pv, fully masked
}

// ---------------------------------------------------------------------------
// 4. read = P @ v. A (p-hat) via cp.async; rescale f applied to A fragments
//    (per-k only, since each warp tile sits in one 64-row segment).
// ---------------------------------------------------------------------------
__global__ __launch_bounds__(128, 2)
void pv_kernel(float* __restrict__ out)
{
    extern __shared__ float dsm[];
    float* As = dsm;                  // [3][A_STG]
    float* Bs = dsm + 3 * A_STG;      // [3][B_STG]

    const int b = blockIdx.z;
    const int rTile = (gridDim.y - 1) - blockIdx.y;   // heavy tiles first
    const int rBase = rTile * 128;
    const int cBase = blockIdx.x * 128;
    const float* A  = g_logits + (size_t)b * T * T;
    const float* Bm = g_v      + (size_t)b * T * C;

    const int tid = threadIdx.x, lane = tid & 31, warp = tid >> 5;
    const int mw = (warp >> 1) * 64, nw = (warp & 1) * 64;
    const int r = lane >> 2, cc = lane & 3;
    const int quad = lane >> 3, qi = lane & 7;
    const uint32_t aLane = ((mw + (quad & 1) * 8 + qi) * AK + (quad >> 1) * 4) * 4;

    const int arow = tid;
    const int brow = tid >> 3, bcol = (tid & 7) * 16;
    const float* Asrc = A  + (size_t)(rBase + arow) * T;
    const float* Bsrc = Bm + (size_t)brow * C + cBase + bcol;
    const float* Frow = g_pm + (size_t)((rBase + mw) >> 6) * M_TOT + b * T;  // per-warp segment
    uint32_t adst[3], bdst[3], aAddrs[3];
#pragma unroll
    for (int s = 0; s < 3; ++s) {
        adst[s] = smem_u32(&As[s * A_STG + arow * AK]);
        bdst[s] = smem_u32(&Bs[s * B_STG + brow * 136 + bcol]);
        aAddrs[s] = smem_u32(&As[s * A_STG]) + aLane;
    }

    auto issue = [&](int st, int k0) {
#pragma unroll
        for (int j = 0; j < 4; ++j)
            CP16(adst[st] + j * 16, Asrc + k0 + j * 4);
#pragma unroll
        for (int j = 0; j < 4; ++j)
            CP16(bdst[st] + j * 16, Bsrc + (size_t)k0 * C + j * 4);
        CP_COMMIT();
    };

    const int NIT = (rBase + 128) / 16;

    float fc[4], fn[4];
    auto loadF = [&](float fv[4], int k0) {
        fv[0] = Frow[k0 + cc];
        fv[1] = Frow[k0 + cc + 4];
        fv[2] = Frow[k0 + 8 + cc];
        fv[3] = Frow[k0 + 8 + cc + 4];
    };

    issue(0, 0);
    issue(1, 16);
    loadF(fc, 0);

    float acc[4][8][4] = {};
    for (int it = 0; it < NIT; ++it) {
        if (it + 1 < NIT) CP_WAIT(1); else CP_WAIT(0);
        __syncthreads();
        if (it + 2 < NIT) issue((it + 2) % 3, (it + 2) * 16);
        if (it + 1 < NIT) loadF(fn, (it + 1) * 16);
        const int st = it % 3;
        mma_consume_f(aAddrs[st], &Bs[st * B_STG], nw, r, cc, fc, acc);
        if (it + 1 < NIT) {
#pragma unroll
            for (int j = 0; j < 4; ++j) fc[j] = fn[j];
        }
    }

#pragma unroll
    for (int mi = 0; mi < 4; ++mi) {
#pragma unroll
        for (int ni = 0; ni < 8; ++ni) {
            const int row = rBase + mw + mi * 16 + r;
            const int col = cBase + nw + ni * 8 + 2 * cc;
            float* d0 = out + ((size_t)(b * T + row) * 1024) + 512 + col;
            float* d1 = out + ((size_t)(b * T + row + 8) * 1024) + 512 + col;
            *(float2*)d0 = make_float2(acc[mi][ni][0], acc[mi][ni][1]);
            *(float2*)d1 = make_float2(acc[mi][ni][2], acc[mi][ni][3]);
        }
    }
}

// ---------------------------------------------------------------------------
extern "C" void kernel_launch(void* const* d_in, const int* in_sizes, int n_in,
                              void* d_out, int out_size)
{
    const float* x  = (const float*)d_in[0];
    const float* Wq = (const float*)d_in[1];
    const float* bq = (const float*)d_in[2];
    const float* Wk = (const float*)d_in[3];
    const float* bk = (const float*)d_in[4];
    const float* Wv = (const float*)d_in[5];
    const float* bv = (const float*)d_in[6];
    float* out = (float*)d_out;

    cudaFuncSetAttribute(qkv_kernel,    cudaFuncAttributeMaxDynamicSharedMemorySize, SMEM_AB);
    cudaFuncSetAttribute(logits_kernel, cudaFuncAttributeMaxDynamicSharedMemorySize, SMEM_AA);
    cudaFuncSetAttribute(pv_kernel,     cudaFuncAttributeMaxDynamicSharedMemorySize, SMEM_AB);

    qkv_kernel<<<dim3(C / 128, M_TOT / 128, 3), 128, SMEM_AB>>>(x, Wq, bq, Wk, bk, Wv, bv, out);
    logits_kernel<<<dim3(T / 128, T / 128, BATCH), 128, SMEM_AA>>>();
    colmerge_kernel<<<M_TOT / 256, 256>>>();
    pv_kernel<<<dim3(C / 128, T / 128, BATCH), 128, SMEM_AB>>>(out);
}

// round 16
// speedup vs baseline: 1.0357x; 1.0357x over previous
#include <cuda_runtime.h>
#include <cstdint>

// Problem constants
constexpr int BATCH = 8;
constexpr int T = 2048;
constexpr int C = 512;                 // IN_CH = KEY = VAL = 512
constexpr int M_TOT = BATCH * T;       // 16384
constexpr int NCHUNK = 32;             // per-64-row-segment softmax partials
constexpr float SCALE = 0.044194173824159216f; // 1/sqrt(512)

constexpr int KT = 32;                 // k-depth per stage
constexpr int AK = 36;                 // padded k-stride for [m][k] smem tiles
constexpr int A_STG = 128 * AK;        // floats per A stage (4608)
constexpr int B_STG = KT * 136;        // floats per B stage (4352)
constexpr int SMEM_AB = 3 * (A_STG + B_STG) * 4;   // qkv / pv dynamic smem (107.5KB)
constexpr int SMEM_AA = 3 * (2 * A_STG) * 4;       // logits dynamic smem (110.6KB)

// Scratch (device globals: allocation-free rule)
__device__ float g_q[M_TOT * C];       // pre-scaled by SCALE
__device__ float g_k[M_TOT * C];
__device__ float g_v[M_TOT * C];
__device__ float g_logits[(size_t)BATCH * T * T];   // exp(l - m_seg), 0 above diag
__device__ float g_pm[(size_t)NCHUNK * M_TOT];      // partial max -> then rescale factor f
__device__ float g_pd[(size_t)NCHUNK * M_TOT];      // partial denom

// ---------------------------------------------------------------------------
// helpers
// ---------------------------------------------------------------------------
__device__ __forceinline__ void mma_tf32(float d[4], const uint32_t a[4], const uint32_t b[2]) {
    asm volatile(
        "mma.sync.aligned.m16n8k8.row.col.f32.tf32.tf32.f32 "
        "{%0,%1,%2,%3}, {%4,%5,%6,%7}, {%8,%9}, {%0,%1,%2,%3};\n"
        : "+f"(d[0]), "+f"(d[1]), "+f"(d[2]), "+f"(d[3])
        : "r"(a[0]), "r"(a[1]), "r"(a[2]), "r"(a[3]), "r"(b[0]), "r"(b[1]));
}
__device__ __forceinline__ uint32_t smem_u32(const void* p) {
    return (uint32_t)__cvta_generic_to_shared(p);
}
__device__ __forceinline__ void ldsm4(uint32_t f[4], uint32_t addr) {
    asm volatile("ldmatrix.sync.aligned.m8n8.x4.shared.b16 {%0,%1,%2,%3}, [%4];"
                 : "=r"(f[0]), "=r"(f[1]), "=r"(f[2]), "=r"(f[3]) : "r"(addr));
}
#define CP16(dst, src) asm volatile("cp.async.ca.shared.global [%0], [%1], 16;" :: "r"(dst), "l"(src))
#define CP_COMMIT()    asm volatile("cp.async.commit_group;")
#define CP_WAIT(n)     asm volatile("cp.async.wait_group %0;" :: "n"(n))

// ---------------------------------------------------------------------------
// MMA consume: 128x128xKT tile; 8 warps of 64x32.
// aAddr: smem addr of A stage base + per-lane ldmatrix offset (incl. mw).
// If BNK: bAddr likewise for [n][AK] B tile; else BsKN points at [KT][136].
// ---------------------------------------------------------------------------
template<bool BNK>
__device__ __forceinline__ void mma_consume(uint32_t aAddr, uint32_t bAddr,
                                            const float* __restrict__ BsKN,
                                            int nw, int r, int c,
                                            float acc[4][4][4])
{
#pragma unroll
    for (int ks = 0; ks < 4; ++ks) {
        const int kkB = ks * 32;          // 8 floats -> 32 bytes
        uint32_t af[4][4], bf[4][2];
#pragma unroll
        for (int mi = 0; mi < 4; ++mi)
            ldsm4(af[mi], aAddr + mi * (16 * AK * 4) + kkB);
        if (BNK) {
#pragma unroll
            for (int p = 0; p < 2; ++p) {
                uint32_t t[4];
                ldsm4(t, bAddr + p * (16 * AK * 4) + kkB);
                bf[2 * p][0] = t[0]; bf[2 * p][1] = t[1];
                bf[2 * p + 1][0] = t[2]; bf[2 * p + 1][1] = t[3];
            }
        } else {
            const int kk = ks * 8;
#pragma unroll
            for (int ni = 0; ni < 4; ++ni) {
                const int n = nw + ni * 8 + r;
                bf[ni][0] = __float_as_uint(BsKN[(kk + c) * 136 + n]);
                bf[ni][1] = __float_as_uint(BsKN[(kk + c + 4) * 136 + n]);
            }
        }
#pragma unroll
        for (int mi = 0; mi < 4; ++mi)
#pragma unroll
            for (int ni = 0; ni < 4; ++ni)
                mma_tf32(acc[mi][ni], af[mi], bf[ni]);
    }
}

// pv variant: A fragments scaled by per-k rescale factors fv[8] (f depends
// only on k within a warp: each 64-row warp tile sits in one 64-row segment).
__device__ __forceinline__ void mma_consume_f(uint32_t aAddr,
                                              const float* __restrict__ BsKN,
                                              int nw, int r, int c,
                                              const float fv[8],
                                              float acc[4][4][4])
{
#pragma unroll
    for (int ks = 0; ks < 4; ++ks) {
        const int kkB = ks * 32;
        const float fa = fv[ks * 2], fb = fv[ks * 2 + 1];
        uint32_t af[4][4], bf[4][2];
#pragma unroll
        for (int mi = 0; mi < 4; ++mi) {
            ldsm4(af[mi], aAddr + mi * (16 * AK * 4) + kkB);
            af[mi][0] = __float_as_uint(__uint_as_float(af[mi][0]) * fa);
            af[mi][1] = __float_as_uint(__uint_as_float(af[mi][1]) * fa);
            af[mi][2] = __float_as_uint(__uint_as_float(af[mi][2]) * fb);
            af[mi][3] = __float_as_uint(__uint_as_float(af[mi][3]) * fb);
        }
        const int kk = ks * 8;
#pragma unroll
        for (int ni = 0; ni < 4; ++ni) {
            const int n = nw + ni * 8 + r;
            bf[ni][0] = __float_as_uint(BsKN[(kk + c) * 136 + n]);
            bf[ni][1] = __float_as_uint(BsKN[(kk + c + 4) * 136 + n]);
        }
#pragma unroll
        for (int mi = 0; mi < 4; ++mi)
#pragma unroll
            for (int ni = 0; ni < 4; ++ni)
                mma_tf32(acc[mi][ni], af[mi], bf[ni]);
    }
}

// Fragment->global: acc[mi][ni][reg]:
//   row = rBase + mw + mi*16 + (lane>>2) + (reg>=2 ? 8 : 0)
//   col = cBase + nw + ni*8  + 2*(lane&3) + (reg&1)

// ---------------------------------------------------------------------------
// 1. QKV projection. 256 threads, 8 warps of 64x32; 3-stage K=32 ring.
//    Blocks (z==0, bx==0) additionally stream x into out[:, 0:512].
// ---------------------------------------------------------------------------
__global__ __launch_bounds__(256, 2)
void qkv_kernel(const float* __restrict__ x,
                const float* __restrict__ Wq, const float* __restrict__ bq,
                const float* __restrict__ Wk, const float* __restrict__ bk,
                const float* __restrict__ Wv, const float* __restrict__ bv,
                float* __restrict__ xout)
{
    extern __shared__ float dsm[];
    float* As = dsm;                  // [3][A_STG]
    float* Bs = dsm + 3 * A_STG;      // [3][B_STG]

    const float* W; const float* bias; float* out; float oscale;
    if (blockIdx.z == 0)      { W = Wq; bias = bq; out = g_q; oscale = SCALE; }
    else if (blockIdx.z == 1) { W = Wk; bias = bk; out = g_k; oscale = 1.0f; }
    else                      { W = Wv; bias = bv; out = g_v; oscale = 1.0f; }

    const int rBase = blockIdx.y * 128;
    const int cBase = blockIdx.x * 128;
    const int tid = threadIdx.x, lane = tid & 31, warp = tid >> 5;
    const int mw = (warp >> 2) * 64, nw = (warp & 3) * 32;
    const int r = lane >> 2, cc = lane & 3;
    const int quad = lane >> 3, qi = lane & 7;
    const uint32_t aLane = ((mw + (quad & 1) * 8 + qi) * AK + (quad >> 1) * 4) * 4;

    const int arow = tid >> 1, aoff = (tid & 1) * 16;   // 16 floats per thread
    const int brow = tid >> 3, bcol = (tid & 7) * 16;
    const float* Asrc = x + (size_t)(rBase + arow) * C + aoff;
    const float* Bsrc = W + (size_t)brow * C + cBase + bcol;
    uint32_t adst[3], bdst[3], aAddrs[3];
#pragma unroll
    for (int s = 0; s < 3; ++s) {
        adst[s] = smem_u32(&As[s * A_STG + arow * AK + aoff]);
        bdst[s] = smem_u32(&Bs[s * B_STG + brow * 136 + bcol]);
        aAddrs[s] = smem_u32(&As[s * A_STG]) + aLane;
    }

    auto issue = [&](int st, int k0) {
#pragma unroll
        for (int j = 0; j < 4; ++j)
            CP16(adst[st] + j * 16, Asrc + k0 + j * 4);
#pragma unroll
        for (int j = 0; j < 4; ++j)
            CP16(bdst[st] + j * 16, Bsrc + (size_t)k0 * C + j * 4);
        CP_COMMIT();
    };

    const bool wx = (blockIdx.z == 0) && (blockIdx.x == 0);
    float acc[4][4][4] = {};
    constexpr int NIT = C / KT;
    issue(0, 0);
    issue(1, KT);
    for (int it = 0; it < NIT; ++it) {
        if (it + 1 < NIT) CP_WAIT(1); else CP_WAIT(0);
        __syncthreads();
        const int st = it % 3;
        if (it + 2 < NIT) issue((it + 2) % 3, (it + 2) * KT);
        if (wx) {
            const float* a = &As[st * A_STG + arow * AK + aoff];
            float* xo = xout + (size_t)(rBase + arow) * 1024 + it * KT + aoff;
#pragma unroll
            for (int j = 0; j < 4; ++j)
                *(float4*)(xo + j * 4) = *(const float4*)(a + j * 4);
        }
        mma_consume<false>(aAddrs[st], 0, &Bs[st * B_STG], nw, r, cc, acc);
    }

#pragma unroll
    for (int mi = 0; mi < 4; ++mi) {
#pragma unroll
        for (int ni = 0; ni < 4; ++ni) {
            const int row = rBase + mw + mi * 16 + r;
            const int col = cBase + nw + ni * 8 + 2 * cc;
            float b0 = bias[col], b1 = bias[col + 1];
            float2 lo, hi;
            lo.x = (acc[mi][ni][0] + b0) * oscale;
            lo.y = (acc[mi][ni][1] + b1) * oscale;
            hi.x = (acc[mi][ni][2] + b0) * oscale;
            hi.y = (acc[mi][ni][3] + b1) * oscale;
            *(float2*)&out[(size_t)row * C + col]       = lo;
            *(float2*)&out[(size_t)(row + 8) * C + col] = hi;
        }
    }
}

// ---------------------------------------------------------------------------
// 2. logits = q . k^T (3-stage K=32 ring, ldmatrix both operands).
//    Per-warp 64-row column-segment softmax; stores exp(l - m_seg), 0 above
//    diag; (m_seg, sum) partials to g_pm/g_pd[chunk = 2*by + (mw>>6)].
// ---------------------------------------------------------------------------
__global__ __launch_bounds__(256, 2)
void logits_kernel()
{
    const int bx = blockIdx.x, by = blockIdx.y, b = blockIdx.z;
    if (bx > by) return;
    extern __shared__ float dsm[];
    float* As = dsm;                  // [3][A_STG]
    float* Bn = dsm + 3 * A_STG;      // [3][A_STG]

    const int rBase = by * 128;
    const int cBase = bx * 128;
    const float* A  = g_q + (size_t)b * T * C;
    const float* Bm = g_k + (size_t)b * T * C;
    float* Cp = g_logits + (size_t)b * T * T;

    const int tid = threadIdx.x, lane = tid & 31, warp = tid >> 5;
    const int mw = (warp >> 2) * 64, nw = (warp & 3) * 32;
    const int r = lane >> 2, cc = lane & 3;
    const int quad = lane >> 3, qi = lane & 7;
    const uint32_t aLane = ((mw + (quad & 1) * 8 + qi) * AK + (quad >> 1) * 4) * 4;
    const uint32_t bLane = ((nw + (quad >> 1) * 8 + qi) * AK + (quad & 1) * 4) * 4;

    const int arow = tid >> 1, aoff = (tid & 1) * 16;
    const float* Asrc = A  + (size_t)(rBase + arow) * C + aoff;
    const float* Bsrc = Bm + (size_t)(cBase + arow) * C + aoff;
    uint32_t adst[3], bdst[3], aAddrs[3], bAddrs[3];
#pragma unroll
    for (int s = 0; s < 3; ++s) {
        adst[s] = smem_u32(&As[s * A_STG + arow * AK + aoff]);
        bdst[s] = smem_u32(&Bn[s * A_STG + arow * AK + aoff]);
        aAddrs[s] = smem_u32(&As[s * A_STG]) + aLane;
        bAddrs[s] = smem_u32(&Bn[s * A_STG]) + bLane;
    }

    auto issue = [&](int st, int k0) {
#pragma unroll
        for (int j = 0; j < 4; ++j)
            CP16(adst[st] + j * 16, Asrc + k0 + j * 4);
#pragma unroll
        for (int j = 0; j < 4; ++j)
            CP16(bdst[st] + j * 16, Bsrc + k0 + j * 4);
        CP_COMMIT();
    };

    float acc[4][4][4] = {};
    constexpr int NIT = C / KT;
    issue(0, 0);
    issue(1, KT);
    for (int it = 0; it < NIT; ++it) {
        if (it + 1 < NIT) CP_WAIT(1); else CP_WAIT(0);
        __syncthreads();
        const int st = it % 3;
        if (it + 2 < NIT) issue((it + 2) % 3, (it + 2) * KT);
        mma_consume<true>(aAddrs[st], bAddrs[st], nullptr, nw, r, cc, acc);
    }

    // per-warp 64-row column-segment stats; acc -> exp(v - m_seg) in place
    const bool diag = (bx == by);
    float mcol[8], dcol[8];
#pragma unroll
    for (int ni = 0; ni < 4; ++ni) {
#pragma unroll
        for (int sub = 0; sub < 2; ++sub) {
            const int j = ni * 2 + sub;
            const int sl = nw + ni * 8 + 2 * cc + sub;   // column within tile
            float m = -1e30f;
#pragma unroll
            for (int mi = 0; mi < 4; ++mi)
#pragma unroll
                for (int h = 0; h < 2; ++h) {
                    const int tl = mw + mi * 16 + r + h * 8;
                    const float v = acc[mi][ni][h * 2 + sub];
                    if ((!diag || tl >= sl) && v > m) m = v;
                }
#pragma unroll
            for (int off = 4; off < 32; off <<= 1)
                m = fmaxf(m, __shfl_xor_sync(0xffffffffu, m, off));
            float d = 0.f;
#pragma unroll
            for (int mi = 0; mi < 4; ++mi)
#pragma unroll
                for (int h = 0; h < 2; ++h) {
                    const int tl = mw + mi * 16 + r + h * 8;
                    const float v = acc[mi][ni][h * 2 + sub];
                    const float p = (!diag || tl >= sl) ? __expf(v - m) : 0.0f;
                    acc[mi][ni][h * 2 + sub] = p;
                    d += p;
                }
#pragma unroll
            for (int off = 4; off < 32; off <<= 1)
                d += __shfl_xor_sync(0xffffffffu, d, off);
            mcol[j] = m; dcol[j] = d;
        }
    }

    // write p-hat tile
#pragma unroll
    for (int mi = 0; mi < 4; ++mi) {
#pragma unroll
        for (int ni = 0; ni < 4; ++ni) {
            const int row = rBase + mw + mi * 16 + r;
            const int col = cBase + nw + ni * 8 + 2 * cc;
            *(float2*)&Cp[(size_t)row * T + col]       = make_float2(acc[mi][ni][0], acc[mi][ni][1]);
            *(float2*)&Cp[(size_t)(row + 8) * T + col] = make_float2(acc[mi][ni][2], acc[mi][ni][3]);
        }
    }

    // write segment partials (chunk = 64-row granularity)
    if (r == 0) {
        const int chw = 2 * by + (mw >> 6);
#pragma unroll
        for (int j = 0; j < 8; ++j) {
            const int colg = cBase + nw + (j >> 1) * 8 + 2 * cc + (j & 1);
            g_pm[(size_t)chw * M_TOT + b * T + colg] = mcol[j];
            g_pd[(size_t)chw * M_TOT + b * T + colg] = dcol[j];
        }
    }
}

// ---------------------------------------------------------------------------
// 3. Merge segment partials; overwrite g_pm with rescale factors
//    f[ch][s] = exp(m_seg - cmax) / sum. Boundary chunk (fully masked) = 0.
// ---------------------------------------------------------------------------
__global__ void colmerge_kernel()
{
    const int i = blockIdx.x * blockDim.x + threadIdx.x;
    const int s = i & (T - 1);
    const int ch0 = s >> 6;
    float m = -1e30f, d = 0.f;
    for (int ch = ch0; ch < NCHUNK; ++ch) {
        float m2 = g_pm[(size_t)ch * M_TOT + i], d2 = g_pd[(size_t)ch * M_TOT + i];
        float nm = fmaxf(m, m2);
        d = d * __expf(m - nm) + d2 * __expf(m2 - nm);
        m = nm;
    }
    const float inv = 1.0f / d;
    for (int ch = ch0; ch < NCHUNK; ++ch) {
        float m2 = g_pm[(size_t)ch * M_TOT + i];
        g_pm[(size_t)ch * M_TOT + i] = __expf(m2 - m) * inv;
    }
    if (ch0 > 0) g_pm[(size_t)(ch0 - 1) * M_TOT + i] = 0.0f;  // read by pv, fully masked
}

// ---------------------------------------------------------------------------
// 4. read = P @ v. A (p-hat) via cp.async; rescale f applied to A fragments
//    (per-k only: each 64-row warp tile sits in one 64-row segment).
// ---------------------------------------------------------------------------
__global__ __launch_bounds__(256, 2)
void pv_kernel(float* __restrict__ out)
{
    extern __shared__ float dsm[];
    float* As = dsm;                  // [3][A_STG]
    float* Bs = dsm + 3 * A_STG;      // [3][B_STG]

    const int b = blockIdx.z;
    const int rTile = (gridDim.y - 1) - blockIdx.y;   // heavy tiles first
    const int rBase = rTile * 128;
    const int cBase = blockIdx.x * 128;
    const float* A  = g_logits + (size_t)b * T * T;
    const float* Bm = g_v      + (size_t)b * T * C;

    const int tid = threadIdx.x, lane = tid & 31, warp = tid >> 5;
    const int mw = (warp >> 2) * 64, nw = (warp & 3) * 32;
    const int r = lane >> 2, cc = lane & 3;
    const int quad = lane >> 3, qi = lane & 7;
    const uint32_t aLane = ((mw + (quad & 1) * 8 + qi) * AK + (quad >> 1) * 4) * 4;

    const int arow = tid >> 1, aoff = (tid & 1) * 16;
    const int brow = tid >> 3, bcol = (tid & 7) * 16;
    const float* Asrc = A  + (size_t)(rBase + arow) * T + aoff;
    const float* Bsrc = Bm + (size_t)brow * C + cBase + bcol;
    const float* Frow = g_pm + (size_t)((rBase + mw) >> 6) * M_TOT + b * T;  // per-warp segment
    uint32_t adst[3], bdst[3], aAddrs[3];
#pragma unroll
    for (int s = 0; s < 3; ++s) {
        adst[s] = smem_u32(&As[s * A_STG + arow * AK + aoff]);
        bdst[s] = smem_u32(&Bs[s * B_STG + brow * 136 + bcol]);
        aAddrs[s] = smem_u32(&As[s * A_STG]) + aLane;
    }

    auto issue = [&](int st, int k0) {
#pragma unroll
        for (int j = 0; j < 4; ++j)
            CP16(adst[st] + j * 16, Asrc + k0 + j * 4);
#pragma unroll
        for (int j = 0; j < 4; ++j)
            CP16(bdst[st] + j * 16, Bsrc + (size_t)k0 * C + j * 4);
        CP_COMMIT();
    };

    const int NIT = (rBase + 128) / KT;

    float fc[8], fn[8];
    auto loadF = [&](float fv[8], int k0) {
#pragma unroll
        for (int ks = 0; ks < 4; ++ks) {
            fv[ks * 2]     = Frow[k0 + ks * 8 + cc];
            fv[ks * 2 + 1] = Frow[k0 + ks * 8 + cc + 4];
        }
    };

    issue(0, 0);
    issue(1, KT);
    loadF(fc, 0);

    float acc[4][4][4] = {};
    for (int it = 0; it < NIT; ++it) {
        if (it + 1 < NIT) CP_WAIT(1); else CP_WAIT(0);
        __syncthreads();
        if (it + 2 < NIT) issue((it + 2) % 3, (it + 2) * KT);
        if (it + 1 < NIT) loadF(fn, (it + 1) * KT);
        const int st = it % 3;
        mma_consume_f(aAddrs[st], &Bs[st * B_STG], nw, r, cc, fc, acc);
        if (it + 1 < NIT) {
#pragma unroll
            for (int j = 0; j < 8; ++j) fc[j] = fn[j];
        }
    }

#pragma unroll
    for (int mi = 0; mi < 4; ++mi) {
#pragma unroll
        for (int ni = 0; ni < 4; ++ni) {
            const int row = rBase + mw + mi * 16 + r;
            const int col = cBase + nw + ni * 8 + 2 * cc;
            float* d0 = out + ((size_t)(b * T + row) * 1024) + 512 + col;
            float* d1 = out + ((size_t)(b * T + row + 8) * 1024) + 512 + col;
            *(float2*)d0 = make_float2(acc[mi][ni][0], acc[mi][ni][1]);
            *(float2*)d1 = make_float2(acc[mi][ni][2], acc[mi][ni][3]);
        }
    }
}

// ---------------------------------------------------------------------------
extern "C" void kernel_launch(void* const* d_in, const int* in_sizes, int n_in,
                              void* d_out, int out_size)
{
    const float* x  = (const float*)d_in[0];
    const float* Wq = (const float*)d_in[1];
    const float* bq = (const float*)d_in[2];
    const float* Wk = (const float*)d_in[3];
    const float* bk = (const float*)d_in[4];
    const float* Wv = (const float*)d_in[5];
    const float* bv = (const float*)d_in[6];
    float* out = (float*)d_out;

    cudaFuncSetAttribute(qkv_kernel,    cudaFuncAttributeMaxDynamicSharedMemorySize, SMEM_AB);
    cudaFuncSetAttribute(logits_kernel, cudaFuncAttributeMaxDynamicSharedMemorySize, SMEM_AA);
    cudaFuncSetAttribute(pv_kernel,     cudaFuncAttributeMaxDynamicSharedMemorySize, SMEM_AB);

    qkv_kernel<<<dim3(C / 128, M_TOT / 128, 3), 256, SMEM_AB>>>(x, Wq, bq, Wk, bk, Wv, bv, out);
    logits_kernel<<<dim3(T / 128, T / 128, BATCH), 256, SMEM_AA>>>();
    colmerge_kernel<<<M_TOT / 256, 256>>>();
    pv_kernel<<<dim3(C / 128, T / 128, BATCH), 256, SMEM_AB>>>(out);
}